// round 11
// baseline (speedup 1.0000x reference)
#include <cuda_runtime.h>
#include <math.h>

// Problem constants (fixed by setup_inputs)
#define B_  2
#define T_  8
#define M_  900
#define H_  27
#define W_  27
#define D_  1024
#define PATCH_ 14

#define NBLK   M_                          // 900 blocks, one per track m (both batches)
#define NPAIR_DENOM (B_ * (T_ - 1) * M_)   // 12600, mean denominator

__device__ float        g_partials[NBLK];
__device__ unsigned int g_done = 0;   // reset by the last block each launch

// L1 over 4 dims: abs folds into FADD source modifiers
__device__ __forceinline__ float l1_4(const float4& a, const float4& b)
{
    float d0 = a.x - b.x, d1 = a.y - b.y, d2 = a.z - b.z, d3 = a.w - b.w;
    return (fabsf(d0) + fabsf(d1)) + (fabsf(d2) + fabsf(d3));
}

__global__ __launch_bounds__(256, 6)      // 42-reg budget -> 6 blocks/SM (R8 proven)
void gather_l1_masked_kernel(const float* __restrict__ features,
                             const float* __restrict__ tracks,
                             const int* __restrict__ vis,   // bool stored as int32
                             float* __restrict__ out)
{
    const int m    = blockIdx.x;          // 0..899
    const int tid  = threadIdx.x;         // 256 threads = 1024 floats / 4
    const int lane = tid & 31;
    const int wid  = tid >> 5;

    // --- Lanes 0..15: lane<8 -> (b=0, t=lane); lane>=8 -> (b=1, t=lane-8).
    unsigned my_off = 0;
    int      my_vis = 0;
    if (lane < 2 * T_) {
        const int bb = lane >> 3;
        const int t  = lane & 7;
        const float2 tr = *(const float2*)(tracks
            + (unsigned)(((bb * T_ + t) * M_ + m) * 2));
        // nearest patch center c_j = 14j+7 -> j = clamp(floor(x/14), 0, 26)
        int j = (int)floorf(tr.x * (1.0f / PATCH_));
        int i = (int)floorf(tr.y * (1.0f / PATCH_));
        j = min(W_ - 1, max(0, j));
        i = min(H_ - 1, max(0, i));
        my_off = (unsigned)((bb * T_ + t) * (H_ * W_) + i * W_ + j) << 10;
        my_vis = vis[(unsigned)((bb * T_ + t) * M_ + m)];
    }
    const unsigned tcol = (unsigned)tid << 2;

    float acc = 0.0f;

#pragma unroll
    for (int bb = 0; bb < B_; bb++) {
        const int sb = bb * T_;
        unsigned off[T_];
        int      vz[T_];
        float    fv[T_];
#pragma unroll
        for (int t = 0; t < T_; t++) {
            off[t] = __shfl_sync(0xffffffffu, my_off, sb + t);
            vz[t]  = __shfl_sync(0xffffffffu, my_vis, sb + t);
            fv[t]  = (float)vz[t];
        }

        // --- Dead-row redirect: a row contributes only if visible AND it has a
        // visible partner (t-1, t+1, or frame 0 for ref pairs). Dead rows load
        // offset 0 instead: same 4KB row grid-wide -> L1/L2 hot, ~no DRAM cost.
        // Compute below stays unconditional; dead rows are multiplied by 0.0.
        {
            int any17 = vz[1] | vz[2] | vz[3] | vz[4] | vz[5] | vz[6] | vz[7];
            if (!(vz[0] & any17)) off[0] = 0u;
#pragma unroll
            for (int t = 1; t < T_ - 1; t++)
                if (!(vz[t] & (vz[t - 1] | vz[t + 1] | vz[0]))) off[t] = 0u;
            if (!(vz[T_ - 1] & (vz[T_ - 2] | vz[0]))) off[T_ - 1] = 0u;
        }

        // --- Gather 8 rows; 8 independent LDG.128 per thread (full MLP).
        float4 pf[T_];
#pragma unroll
        for (int t = 0; t < T_; t++)
            pf[t] = *(const float4*)(features + (off[t] + tcol));

        // --- 13 distinct pairs; pair (0,1) serves both consec and ref terms.
        float l01 = l1_4(pf[0], pf[1]);
        float m01 = fv[0] * fv[1];
        float acc_c = m01 * l01;
        float acc_r = m01 * l01;
#pragma unroll
        for (int t = 1; t < T_ - 1; t++) {
            acc_c = fmaf(fv[t] * fv[t + 1], l1_4(pf[t], pf[t + 1]), acc_c);
            acc_r = fmaf(fv[0] * fv[t + 1], l1_4(pf[0], pf[t + 1]), acc_r);
        }
        acc += acc_c + acc_r;             // fixed order -> deterministic
    }

    // --- Block reduction: warp shuffle, then 8 warp sums via shared
#pragma unroll
    for (int o = 16; o > 0; o >>= 1)
        acc += __shfl_down_sync(0xffffffffu, acc, o);

    __shared__ float s_warp[8];
    if (lane == 0) s_warp[wid] = acc;
    __syncthreads();

    __shared__ bool s_is_last;
    if (tid == 0) {
        float s = 0.0f;
#pragma unroll
        for (int w = 0; w < 8; w++) s += s_warp[w];
        g_partials[m] = s;
        __threadfence();
        unsigned int prev = atomicAdd(&g_done, 1u);
        s_is_last = (prev == NBLK - 1);
    }
    __syncthreads();

    // --- Last block reduces all partials (fixed order -> deterministic)
    if (s_is_last) {
        double dacc = 0.0;
#pragma unroll
        for (int k = 0; k < (NBLK + 255) / 256; k++) {
            int i = k * 256 + tid;
            if (i < NBLK) dacc += (double)g_partials[i];
        }
#pragma unroll
        for (int o = 16; o > 0; o >>= 1)
            dacc += __shfl_down_sync(0xffffffffu, dacc, o);

        __shared__ double s_dwarp[8];
        if (lane == 0) s_dwarp[wid] = dacc;
        __syncthreads();
        if (tid == 0) {
            double s = 0.0;
#pragma unroll
            for (int w = 0; w < 8; w++) s += s_dwarp[w];
            out[0] = (float)(0.01 * s / (double)NPAIR_DENOM);
            g_done = 0;                   // reset for next graph replay
        }
    }
}

extern "C" void kernel_launch(void* const* d_in, const int* in_sizes, int n_in,
                              void* d_out, int out_size)
{
    const float* features = (const float*)d_in[0];  // [B*T, H*W, D] f32
    const float* tracks   = (const float*)d_in[1];  // [B, T, M, 2]  f32
    const int*   vis      = (const int*)d_in[2];    // [B, T, M]     bool->int32
    float*       out      = (float*)d_out;

    gather_l1_masked_kernel<<<NBLK, 256>>>(features, tracks, vis, out);
}

// round 12
// speedup vs baseline: 1.1901x; 1.1901x over previous
#include <cuda_runtime.h>
#include <math.h>

// Problem constants (fixed by setup_inputs)
#define B_  2
#define T_  8
#define M_  900
#define H_  27
#define W_  27
#define D_  1024
#define PATCH_ 14

#define NBLK   M_                          // 900 blocks, one per track m (both batches)
#define NPAIR_DENOM (B_ * (T_ - 1) * M_)   // 12600, mean denominator
#define FP_SCALE 4194304.0f                // 2^22 fixed-point scale

// Single deterministic accumulator: bits [0:52) fixed-point sum, bits [52:64) block count.
__device__ unsigned long long g_sum = 0ull;   // reset by the last block each launch

// L1 over 4 dims: abs folds into FADD source modifiers
__device__ __forceinline__ float l1_4(const float4& a, const float4& b)
{
    float d0 = a.x - b.x, d1 = a.y - b.y, d2 = a.z - b.z, d3 = a.w - b.w;
    return (fabsf(d0) + fabsf(d1)) + (fabsf(d2) + fabsf(d3));
}

__global__ __launch_bounds__(256, 6)      // 42-reg budget -> 6 blocks/SM (R8-proven)
void gather_l1_atomic_kernel(const float* __restrict__ features,
                             const float* __restrict__ tracks,
                             const int* __restrict__ vis,   // bool stored as int32
                             float* __restrict__ out)
{
    const int m    = blockIdx.x;          // 0..899
    const int tid  = threadIdx.x;         // 256 threads = 1024 floats / 4
    const int lane = tid & 31;
    const int wid  = tid >> 5;

    // --- Lanes 0..15: lane<8 -> (b=0, t=lane); lane>=8 -> (b=1, t=lane-8).
    unsigned my_off = 0;
    int      my_vis = 0;
    if (lane < 2 * T_) {
        const int bb = lane >> 3;
        const int t  = lane & 7;
        const float2 tr = *(const float2*)(tracks
            + (unsigned)(((bb * T_ + t) * M_ + m) * 2));
        // nearest patch center c_j = 14j+7 -> j = clamp(floor(x/14), 0, 26)
        int j = (int)floorf(tr.x * (1.0f / PATCH_));
        int i = (int)floorf(tr.y * (1.0f / PATCH_));
        j = min(W_ - 1, max(0, j));
        i = min(H_ - 1, max(0, i));
        my_off = (unsigned)((bb * T_ + t) * (H_ * W_) + i * W_ + j) << 10;
        my_vis = vis[(unsigned)((bb * T_ + t) * M_ + m)];
    }
    const unsigned tcol = (unsigned)tid << 2;

    float acc = 0.0f;

#pragma unroll
    for (int bb = 0; bb < B_; bb++) {
        const int sb = bb * T_;
        unsigned off[T_];
        int      vz[T_];
        float    fv[T_];
#pragma unroll
        for (int t = 0; t < T_; t++) {
            off[t] = __shfl_sync(0xffffffffu, my_off, sb + t);
            vz[t]  = __shfl_sync(0xffffffffu, my_vis, sb + t);
            fv[t]  = (float)vz[t];
        }

        // --- Dead-row redirect: a row contributes only if visible AND it has a
        // visible partner (t-1, t+1, or frame 0). Dead rows load offset 0:
        // same 4KB row grid-wide -> L1/L2 hot, ~no DRAM cost. Compute stays
        // unconditional; dead rows multiply by 0.0.
        {
            int any17 = vz[1] | vz[2] | vz[3] | vz[4] | vz[5] | vz[6] | vz[7];
            if (!(vz[0] & any17)) off[0] = 0u;
#pragma unroll
            for (int t = 1; t < T_ - 1; t++)
                if (!(vz[t] & (vz[t - 1] | vz[t + 1] | vz[0]))) off[t] = 0u;
            if (!(vz[T_ - 1] & (vz[T_ - 2] | vz[0]))) off[T_ - 1] = 0u;
        }

        // --- Gather 8 rows; 8 independent LDG.128 per thread (full MLP).
        float4 pf[T_];
#pragma unroll
        for (int t = 0; t < T_; t++)
            pf[t] = *(const float4*)(features + (off[t] + tcol));

        // --- 13 distinct pairs; pair (0,1) serves both consec and ref terms.
        float l01 = l1_4(pf[0], pf[1]);
        float m01 = fv[0] * fv[1];
        float acc_c = m01 * l01;
        float acc_r = m01 * l01;
#pragma unroll
        for (int t = 1; t < T_ - 1; t++) {
            acc_c = fmaf(fv[t] * fv[t + 1], l1_4(pf[t], pf[t + 1]), acc_c);
            acc_r = fmaf(fv[0] * fv[t + 1], l1_4(pf[0], pf[t + 1]), acc_r);
        }
        acc += acc_c + acc_r;             // fixed order -> deterministic
    }

    // --- Block reduction: warp shuffle, then 8 warp sums via shared
#pragma unroll
    for (int o = 16; o > 0; o >>= 1)
        acc += __shfl_down_sync(0xffffffffu, acc, o);

    __shared__ float s_warp[8];
    if (lane == 0) s_warp[wid] = acc;
    __syncthreads();

    // --- Deterministic fixed-point atomic epilogue (no fence, no spin, no re-read):
    // integer adds commute exactly; count rides in bits [52:64) of the same word.
    if (tid == 0) {
        float s = 0.0f;
#pragma unroll
        for (int w = 0; w < 8; w++) s += s_warp[w];
        unsigned long long mine = (1ull << 52)
                                + (unsigned long long)llrintf(s * FP_SCALE);
        unsigned long long old = atomicAdd(&g_sum, mine);
        if ((old >> 52) == (unsigned long long)(NBLK - 1)) {
            // Last block: total is already in hand. Low 52 bits = fixed-point sum.
            unsigned long long total = (old + mine) & ((1ull << 52) - 1ull);
            out[0] = (float)(0.01 * (double)total
                             / ((double)FP_SCALE * (double)NPAIR_DENOM));
            g_sum = 0ull;                 // reset for next graph replay (all adds done)
        }
    }
}

extern "C" void kernel_launch(void* const* d_in, const int* in_sizes, int n_in,
                              void* d_out, int out_size)
{
    const float* features = (const float*)d_in[0];  // [B*T, H*W, D] f32
    const float* tracks   = (const float*)d_in[1];  // [B, T, M, 2]  f32
    const int*   vis      = (const int*)d_in[2];    // [B, T, M]     bool->int32
    float*       out      = (float*)d_out;

    gather_l1_atomic_kernel<<<NBLK, 256>>>(features, tracks, vis, out);
}